// round 4
// baseline (speedup 1.0000x reference)
#include <cuda_runtime.h>

#define CHUNKS 16
#define RES_DIM 8192
#define NSE 1342177
#define BLOCKS_X 37              // 37*16 = 592 = 148 SMs * 4 blocks -> exactly 1 wave
#define TPB 512

// Second accumulator (device scratch; allocation-free per harness rules).
__device__ float g_acc1[CHUNKS * RES_DIM];

// Kernel 1: out = proj, g_acc1 = 0.
__global__ void ptd_init_kernel(const float* __restrict__ proj, float* __restrict__ out) {
    int i = blockIdx.x * blockDim.x + threadIdx.x;
    if (i < (CHUNKS * RES_DIM) / 4) {
        reinterpret_cast<float4*>(out)[i] = reinterpret_cast<const float4*>(proj)[i];
        reinterpret_cast<float4*>(g_acc1)[i] = make_float4(0.f, 0.f, 0.f, 0.f);
    }
}

// Kernel 2: COO scatter, single-wave grid (592 blocks, 4/SM).
__global__ void __launch_bounds__(TPB)
ptd_scatter_kernel(const float* __restrict__ vals,
                   const int*   __restrict__ rows,
                   const int*   __restrict__ cols,
                   const float* __restrict__ state,
                   float*       __restrict__ out) {
    __shared__ float s[RES_DIM];

    const int chunk = blockIdx.y;
    const size_t base = (size_t)chunk * NSE;
    float* __restrict__ o0 = out + chunk * RES_DIM;
    float* __restrict__ o1 = g_acc1 + chunk * RES_DIM;

    // Stage state[chunk] into shared memory.
    {
        const float4* st4 = reinterpret_cast<const float4*>(state + (size_t)chunk * RES_DIM);
        float4* sh4 = reinterpret_cast<float4*>(s);
        #pragma unroll
        for (int i = threadIdx.x; i < RES_DIM / 4; i += TPB) sh4[i] = st4[i];
    }
    __syncthreads();

    // Alignment split (base not 16B-aligned since NSE is odd).
    const int head = (int)((4 - (base & 3)) & 3);
    const int nvec = (NSE - head) >> 2;
    const int tail = NSE - head - (nvec << 2);

    const float4* __restrict__ v4 = reinterpret_cast<const float4*>(vals + base + head);
    const int4*   __restrict__ r4 = reinterpret_cast<const int4*>(rows + base + head);
    const int4*   __restrict__ c4 = reinterpret_cast<const int4*>(cols + base + head);

    const int stride = BLOCKS_X * TPB;
    int i = blockIdx.x * TPB + threadIdx.x;

    // Main loop, unrolled x4 (16 nnz/thread/iter): 12 streaming LDG.128 up
    // front, then 16 fire-and-forget REDs split across two accumulators.
    for (; i + 3 * stride < nvec; i += 4 * stride) {
        const int j = i + stride, k = i + 2 * stride, l = i + 3 * stride;
        float4 va = __ldcs(v4 + i); float4 vb = __ldcs(v4 + j);
        float4 vc = __ldcs(v4 + k); float4 vd = __ldcs(v4 + l);
        int4   ca = __ldcs(c4 + i); int4   cb = __ldcs(c4 + j);
        int4   cc = __ldcs(c4 + k); int4   cd = __ldcs(c4 + l);
        int4   ra = __ldcs(r4 + i); int4   rb = __ldcs(r4 + j);
        int4   rc = __ldcs(r4 + k); int4   rd = __ldcs(r4 + l);

        atomicAdd(o0 + ra.x, va.x * s[ca.x]);
        atomicAdd(o1 + ra.y, va.y * s[ca.y]);
        atomicAdd(o0 + ra.z, va.z * s[ca.z]);
        atomicAdd(o1 + ra.w, va.w * s[ca.w]);
        atomicAdd(o0 + rb.x, vb.x * s[cb.x]);
        atomicAdd(o1 + rb.y, vb.y * s[cb.y]);
        atomicAdd(o0 + rb.z, vb.z * s[cb.z]);
        atomicAdd(o1 + rb.w, vb.w * s[cb.w]);
        atomicAdd(o0 + rc.x, vc.x * s[cc.x]);
        atomicAdd(o1 + rc.y, vc.y * s[cc.y]);
        atomicAdd(o0 + rc.z, vc.z * s[cc.z]);
        atomicAdd(o1 + rc.w, vc.w * s[cc.w]);
        atomicAdd(o0 + rd.x, vd.x * s[cd.x]);
        atomicAdd(o1 + rd.y, vd.y * s[cd.y]);
        atomicAdd(o0 + rd.z, vd.z * s[cd.z]);
        atomicAdd(o1 + rd.w, vd.w * s[cd.w]);
    }
    for (; i < nvec; i += stride) {
        float4 va = __ldcs(v4 + i);
        int4   ca = __ldcs(c4 + i);
        int4   ra = __ldcs(r4 + i);
        atomicAdd(o0 + ra.x, va.x * s[ca.x]);
        atomicAdd(o1 + ra.y, va.y * s[ca.y]);
        atomicAdd(o0 + ra.z, va.z * s[ca.z]);
        atomicAdd(o1 + ra.w, va.w * s[ca.w]);
    }

    // Head + tail scalars (block x==0 only).
    if (blockIdx.x == 0) {
        if (threadIdx.x < head) {
            const size_t k = base + threadIdx.x;
            atomicAdd(o0 + rows[k], vals[k] * s[cols[k]]);
        }
        if (threadIdx.x >= 32 && threadIdx.x < 32 + tail) {
            const size_t k = base + head + ((size_t)nvec << 2) + (threadIdx.x - 32);
            atomicAdd(o0 + rows[k], vals[k] * s[cols[k]]);
        }
    }
}

// Kernel 3: out = taylor_tanh(out + g_acc1), vectorized.
__global__ void ptd_horner_kernel(float* __restrict__ out) {
    int i = blockIdx.x * blockDim.x + threadIdx.x;
    if (i >= (CHUNKS * RES_DIM) / 4) return;

    const float t  = tanhf(1.6f);
    const float t2 = t * t;
    const float t3 = t2 * t;
    const float t4 = t2 * t2;
    const float t6 = t4 * t2;
    const float c0 = t;
    const float c1 = 1.0f - t2;
    const float c2 = t3 - t;
    const float c3 = -t4 + (4.0f / 3.0f) * t2 - (1.0f / 3.0f);
    const float c4 = (t / 3.0f) * (3.0f * t4 - 5.0f * t2 + 2.0f);
    const float c5 = -t6 + 2.0f * t4 - (17.0f / 15.0f) * t2 + (2.0f / 15.0f);

    float4 a = reinterpret_cast<float4*>(out)[i];
    float4 b = reinterpret_cast<const float4*>(g_acc1)[i];
    float zx = a.x + b.x, zy = a.y + b.y, zz = a.z + b.z, zw = a.w + b.w;
    float4 p;
    p.x = fmaf(zx, fmaf(zx, fmaf(zx, fmaf(zx, fmaf(zx, c5, c4), c3), c2), c1), c0);
    p.y = fmaf(zy, fmaf(zy, fmaf(zy, fmaf(zy, fmaf(zy, c5, c4), c3), c2), c1), c0);
    p.z = fmaf(zz, fmaf(zz, fmaf(zz, fmaf(zz, fmaf(zz, c5, c4), c3), c2), c1), c0);
    p.w = fmaf(zw, fmaf(zw, fmaf(zw, fmaf(zw, fmaf(zw, c5, c4), c3), c2), c1), c0);
    reinterpret_cast<float4*>(out)[i] = p;
}

extern "C" void kernel_launch(void* const* d_in, const int* in_sizes, int n_in,
                              void* d_out, int out_size) {
    const float* proj  = (const float*)d_in[0];
    const float* state = (const float*)d_in[1];
    const float* vals  = (const float*)d_in[2];
    const int*   rows  = (const int*)d_in[3];
    const int*   cols  = (const int*)d_in[4];
    float* out = (float*)d_out;

    {
        int n4 = (CHUNKS * RES_DIM) / 4;
        ptd_init_kernel<<<(n4 + 255) / 256, 256>>>(proj, out);
    }
    {
        dim3 grid(BLOCKS_X, CHUNKS);   // 592 blocks = exactly one wave (4/SM)
        ptd_scatter_kernel<<<grid, TPB>>>(vals, rows, cols, state, out);
    }
    {
        int n4 = (CHUNKS * RES_DIM) / 4;
        ptd_horner_kernel<<<(n4 + 255) / 256, 256>>>(out);
    }
}

// round 5
// speedup vs baseline: 2.2949x; 2.2949x over previous
#include <cuda_runtime.h>

#define CHUNKS 16
#define RES_DIM 8192
#define NSE 1342177
#define BLOCKS_X 18               // 18*16 = 288 blocks = 2/SM (one wave at 1024 thr)
#define TPB 1024

// Kernel 1: COO scatter with shared-memory privatization.
// Each block accumulates into a private 32KB smem histogram (smem atomics),
// then flushes 8192 global REDs. Global atomic count: 21.5M -> 2.36M.
// Block x==0 of each chunk seeds its accumulator with proj (so no init kernel).
__global__ void __launch_bounds__(TPB, 2)
ptd_scatter_kernel(const float* __restrict__ vals,
                   const int*   __restrict__ rows,
                   const int*   __restrict__ cols,
                   const float* __restrict__ state,
                   const float* __restrict__ proj,
                   float*       __restrict__ out) {
    __shared__ float sacc[RES_DIM];            // 32 KB private accumulator

    const int chunk = blockIdx.y;
    const size_t base = (size_t)chunk * NSE;
    const float* __restrict__ s = state + (size_t)chunk * RES_DIM;
    float* __restrict__ o = out + (size_t)chunk * RES_DIM;

    // Seed accumulator: proj for block x==0, zeros otherwise.
    {
        float4* s4 = reinterpret_cast<float4*>(sacc);
        if (blockIdx.x == 0) {
            const float4* p4 = reinterpret_cast<const float4*>(proj + (size_t)chunk * RES_DIM);
            #pragma unroll
            for (int i = threadIdx.x; i < RES_DIM / 4; i += TPB) s4[i] = p4[i];
        } else {
            #pragma unroll
            for (int i = threadIdx.x; i < RES_DIM / 4; i += TPB)
                s4[i] = make_float4(0.f, 0.f, 0.f, 0.f);
        }
    }
    __syncthreads();

    // Alignment split (base not 16B-aligned since NSE is odd).
    const int head = (int)((4 - (base & 3)) & 3);
    const int nvec = (NSE - head) >> 2;
    const int tail = NSE - head - (nvec << 2);

    const float4* __restrict__ v4 = reinterpret_cast<const float4*>(vals + base + head);
    const int4*   __restrict__ r4 = reinterpret_cast<const int4*>(rows + base + head);
    const int4*   __restrict__ c4 = reinterpret_cast<const int4*>(cols + base + head);

    const int stride = BLOCKS_X * TPB;
    int i = blockIdx.x * TPB + threadIdx.x;

    // Main loop, unrolled x2 (8 nnz/thread/iter): 6 streaming LDG.128, then
    // 8 gathers (L1-resident state) and 8 smem atomics.
    for (; i + stride < nvec; i += 2 * stride) {
        const int j = i + stride;
        float4 va = __ldcs(v4 + i); float4 vb = __ldcs(v4 + j);
        int4   ca = __ldcs(c4 + i); int4   cb = __ldcs(c4 + j);
        int4   ra = __ldcs(r4 + i); int4   rb = __ldcs(r4 + j);

        float fa0 = va.x * __ldg(s + ca.x), fa1 = va.y * __ldg(s + ca.y);
        float fa2 = va.z * __ldg(s + ca.z), fa3 = va.w * __ldg(s + ca.w);
        float fb0 = vb.x * __ldg(s + cb.x), fb1 = vb.y * __ldg(s + cb.y);
        float fb2 = vb.z * __ldg(s + cb.z), fb3 = vb.w * __ldg(s + cb.w);

        atomicAdd(sacc + ra.x, fa0);
        atomicAdd(sacc + ra.y, fa1);
        atomicAdd(sacc + ra.z, fa2);
        atomicAdd(sacc + ra.w, fa3);
        atomicAdd(sacc + rb.x, fb0);
        atomicAdd(sacc + rb.y, fb1);
        atomicAdd(sacc + rb.z, fb2);
        atomicAdd(sacc + rb.w, fb3);
    }
    for (; i < nvec; i += stride) {
        float4 va = __ldcs(v4 + i);
        int4   ca = __ldcs(c4 + i);
        int4   ra = __ldcs(r4 + i);
        atomicAdd(sacc + ra.x, va.x * __ldg(s + ca.x));
        atomicAdd(sacc + ra.y, va.y * __ldg(s + ca.y));
        atomicAdd(sacc + ra.z, va.z * __ldg(s + ca.z));
        atomicAdd(sacc + ra.w, va.w * __ldg(s + ca.w));
    }

    // Head + tail scalars (block x==0 only, into its own sacc).
    if (blockIdx.x == 0) {
        if (threadIdx.x < head) {
            const size_t k = base + threadIdx.x;
            atomicAdd(sacc + rows[k], vals[k] * __ldg(s + cols[k]));
        }
        if (threadIdx.x >= 32 && threadIdx.x < 32 + tail) {
            const size_t k = base + head + ((size_t)nvec << 2) + (threadIdx.x - 32);
            atomicAdd(sacc + rows[k], vals[k] * __ldg(s + cols[k]));
        }
    }
    __syncthreads();

    // Flush: 8192 global REDs per block (8 per thread), fire-and-forget.
    #pragma unroll
    for (int k = threadIdx.x; k < RES_DIM; k += TPB) {
        atomicAdd(o + k, sacc[k]);
    }
}

// Kernel 2: in-place Horner evaluation of degree-5 Taylor of tanh(1.6 + z).
// out already holds proj + spmv.
__global__ void ptd_horner_kernel(float* __restrict__ out) {
    int i = blockIdx.x * blockDim.x + threadIdx.x;
    if (i >= (CHUNKS * RES_DIM) / 4) return;

    const float t  = tanhf(1.6f);
    const float t2 = t * t;
    const float t3 = t2 * t;
    const float t4 = t2 * t2;
    const float t6 = t4 * t2;
    const float c0 = t;
    const float c1 = 1.0f - t2;
    const float c2 = t3 - t;
    const float c3 = -t4 + (4.0f / 3.0f) * t2 - (1.0f / 3.0f);
    const float c4 = (t / 3.0f) * (3.0f * t4 - 5.0f * t2 + 2.0f);
    const float c5 = -t6 + 2.0f * t4 - (17.0f / 15.0f) * t2 + (2.0f / 15.0f);

    float4 z = reinterpret_cast<float4*>(out)[i];
    float4 p;
    p.x = fmaf(z.x, fmaf(z.x, fmaf(z.x, fmaf(z.x, fmaf(z.x, c5, c4), c3), c2), c1), c0);
    p.y = fmaf(z.y, fmaf(z.y, fmaf(z.y, fmaf(z.y, fmaf(z.y, c5, c4), c3), c2), c1), c0);
    p.z = fmaf(z.z, fmaf(z.z, fmaf(z.z, fmaf(z.z, fmaf(z.z, c5, c4), c3), c2), c1), c0);
    p.w = fmaf(z.w, fmaf(z.w, fmaf(z.w, fmaf(z.w, fmaf(z.w, c5, c4), c3), c2), c1), c0);
    reinterpret_cast<float4*>(out)[i] = p;
}

extern "C" void kernel_launch(void* const* d_in, const int* in_sizes, int n_in,
                              void* d_out, int out_size) {
    const float* proj  = (const float*)d_in[0];
    const float* state = (const float*)d_in[1];
    const float* vals  = (const float*)d_in[2];
    const int*   rows  = (const int*)d_in[3];
    const int*   cols  = (const int*)d_in[4];
    float* out = (float*)d_out;

    // Zero the accumulator (graph-capturable memset node).
    cudaMemsetAsync(out, 0, (size_t)CHUNKS * RES_DIM * sizeof(float));

    {
        dim3 grid(BLOCKS_X, CHUNKS);   // 288 blocks x 1024 threads, 2/SM
        ptd_scatter_kernel<<<grid, TPB>>>(vals, rows, cols, state, proj, out);
    }
    {
        int n4 = (CHUNKS * RES_DIM) / 4;
        ptd_horner_kernel<<<(n4 + 255) / 256, 256>>>(out);
    }
}

// round 6
// speedup vs baseline: 2.3148x; 1.0087x over previous
#include <cuda_runtime.h>

#define CHUNKS 16
#define RES_DIM 8192
#define NSE 1342177
#define BLOCKS_X 18               // partials per chunk; 18*16 = 288 blocks (2/SM)
#define TPB 1024

// Per-block partial accumulators: 16 chunks x 18 blocks x 8192 floats = 9.4 MB.
__device__ float g_part[CHUNKS * BLOCKS_X * RES_DIM];

// Kernel 1: COO scatter with shared-memory privatization.
// Each block accumulates into a private 32KB smem histogram (smem atomics),
// then flushes with plain float4 stores into its own scratch slice.
// NO global atomics anywhere.
__global__ void __launch_bounds__(TPB, 2)
ptd_scatter_kernel(const float* __restrict__ vals,
                   const int*   __restrict__ rows,
                   const int*   __restrict__ cols,
                   const float* __restrict__ state) {
    __shared__ float sacc[RES_DIM];            // 32 KB private accumulator

    const int chunk = blockIdx.y;
    const size_t base = (size_t)chunk * NSE;
    const float* __restrict__ s = state + (size_t)chunk * RES_DIM;

    // Zero the private accumulator.
    {
        float4* s4 = reinterpret_cast<float4*>(sacc);
        #pragma unroll
        for (int i = threadIdx.x; i < RES_DIM / 4; i += TPB)
            s4[i] = make_float4(0.f, 0.f, 0.f, 0.f);
    }
    __syncthreads();

    // Alignment split (base not 16B-aligned since NSE is odd).
    const int head = (int)((4 - (base & 3)) & 3);
    const int nvec = (NSE - head) >> 2;
    const int tail = NSE - head - (nvec << 2);

    const float4* __restrict__ v4 = reinterpret_cast<const float4*>(vals + base + head);
    const int4*   __restrict__ r4 = reinterpret_cast<const int4*>(rows + base + head);
    const int4*   __restrict__ c4 = reinterpret_cast<const int4*>(cols + base + head);

    const int stride = BLOCKS_X * TPB;
    int i = blockIdx.x * TPB + threadIdx.x;

    // Main loop, unrolled x2 (8 nnz/thread/iter): 6 streaming LDG.128, then
    // 8 gathers (L1-resident state) and 8 smem atomics.
    for (; i + stride < nvec; i += 2 * stride) {
        const int j = i + stride;
        float4 va = __ldcs(v4 + i); float4 vb = __ldcs(v4 + j);
        int4   ca = __ldcs(c4 + i); int4   cb = __ldcs(c4 + j);
        int4   ra = __ldcs(r4 + i); int4   rb = __ldcs(r4 + j);

        float fa0 = va.x * __ldg(s + ca.x), fa1 = va.y * __ldg(s + ca.y);
        float fa2 = va.z * __ldg(s + ca.z), fa3 = va.w * __ldg(s + ca.w);
        float fb0 = vb.x * __ldg(s + cb.x), fb1 = vb.y * __ldg(s + cb.y);
        float fb2 = vb.z * __ldg(s + cb.z), fb3 = vb.w * __ldg(s + cb.w);

        atomicAdd(sacc + ra.x, fa0);
        atomicAdd(sacc + ra.y, fa1);
        atomicAdd(sacc + ra.z, fa2);
        atomicAdd(sacc + ra.w, fa3);
        atomicAdd(sacc + rb.x, fb0);
        atomicAdd(sacc + rb.y, fb1);
        atomicAdd(sacc + rb.z, fb2);
        atomicAdd(sacc + rb.w, fb3);
    }
    for (; i < nvec; i += stride) {
        float4 va = __ldcs(v4 + i);
        int4   ca = __ldcs(c4 + i);
        int4   ra = __ldcs(r4 + i);
        atomicAdd(sacc + ra.x, va.x * __ldg(s + ca.x));
        atomicAdd(sacc + ra.y, va.y * __ldg(s + ca.y));
        atomicAdd(sacc + ra.z, va.z * __ldg(s + ca.z));
        atomicAdd(sacc + ra.w, va.w * __ldg(s + ca.w));
    }

    // Head + tail scalars (block x==0 only, into its own sacc).
    if (blockIdx.x == 0) {
        if (threadIdx.x < head) {
            const size_t k = base + threadIdx.x;
            atomicAdd(sacc + rows[k], vals[k] * __ldg(s + cols[k]));
        }
        if (threadIdx.x >= 32 && threadIdx.x < 32 + tail) {
            const size_t k = base + head + ((size_t)nvec << 2) + (threadIdx.x - 32);
            atomicAdd(sacc + rows[k], vals[k] * __ldg(s + cols[k]));
        }
    }
    __syncthreads();

    // Flush: plain vectorized stores to this block's scratch slice (2048 STG.128).
    {
        float4* dst = reinterpret_cast<float4*>(
            g_part + ((size_t)chunk * BLOCKS_X + blockIdx.x) * RES_DIM);
        const float4* src = reinterpret_cast<const float4*>(sacc);
        #pragma unroll
        for (int k = threadIdx.x; k < RES_DIM / 4; k += TPB)
            dst[k] = src[k];
    }
}

// Kernel 2: finalize.  out = taylor_tanh(proj + sum_b partials[b]).
// Reads 9.4 MB coalesced, fuses the reduction with the Horner polynomial.
__global__ void ptd_finalize_kernel(const float* __restrict__ proj,
                                    float* __restrict__ out) {
    int i = blockIdx.x * blockDim.x + threadIdx.x;       // float4 index
    if (i >= (CHUNKS * RES_DIM) / 4) return;

    const int chunk = i / (RES_DIM / 4);

    float4 z = reinterpret_cast<const float4*>(proj)[i];

    const float4* p4 = reinterpret_cast<const float4*>(
        g_part + (size_t)chunk * BLOCKS_X * RES_DIM);
    const int ofs = i - chunk * (RES_DIM / 4);           // float4 offset in chunk
    #pragma unroll
    for (int b = 0; b < BLOCKS_X; b++) {
        float4 p = __ldcs(p4 + (size_t)b * (RES_DIM / 4) + ofs);
        z.x += p.x; z.y += p.y; z.z += p.z; z.w += p.w;
    }

    const float t  = tanhf(1.6f);
    const float t2 = t * t;
    const float t3 = t2 * t;
    const float t4 = t2 * t2;
    const float t6 = t4 * t2;
    const float c0 = t;
    const float c1 = 1.0f - t2;
    const float c2 = t3 - t;
    const float c3 = -t4 + (4.0f / 3.0f) * t2 - (1.0f / 3.0f);
    const float c4 = (t / 3.0f) * (3.0f * t4 - 5.0f * t2 + 2.0f);
    const float c5 = -t6 + 2.0f * t4 - (17.0f / 15.0f) * t2 + (2.0f / 15.0f);

    float4 p;
    p.x = fmaf(z.x, fmaf(z.x, fmaf(z.x, fmaf(z.x, fmaf(z.x, c5, c4), c3), c2), c1), c0);
    p.y = fmaf(z.y, fmaf(z.y, fmaf(z.y, fmaf(z.y, fmaf(z.y, c5, c4), c3), c2), c1), c0);
    p.z = fmaf(z.z, fmaf(z.z, fmaf(z.z, fmaf(z.z, fmaf(z.z, c5, c4), c3), c2), c1), c0);
    p.w = fmaf(z.w, fmaf(z.w, fmaf(z.w, fmaf(z.w, fmaf(z.w, c5, c4), c3), c2), c1), c0);
    reinterpret_cast<float4*>(out)[i] = p;
}

extern "C" void kernel_launch(void* const* d_in, const int* in_sizes, int n_in,
                              void* d_out, int out_size) {
    const float* proj  = (const float*)d_in[0];
    const float* state = (const float*)d_in[1];
    const float* vals  = (const float*)d_in[2];
    const int*   rows  = (const int*)d_in[3];
    const int*   cols  = (const int*)d_in[4];
    float* out = (float*)d_out;

    {
        dim3 grid(BLOCKS_X, CHUNKS);   // 288 blocks x 1024 threads, 2/SM
        ptd_scatter_kernel<<<grid, TPB>>>(vals, rows, cols, state);
    }
    {
        int n4 = (CHUNKS * RES_DIM) / 4;
        ptd_finalize_kernel<<<(n4 + 255) / 256, 256>>>(proj, out);
    }
}